// round 4
// baseline (speedup 1.0000x reference)
#include <cuda_runtime.h>
#include <cstdint>

#define DD 256
#define WR 129
#define NB 64
#define PI_F 3.14159265358979323846f
#define RUN 8
#define NCH 17   // ceil(129/8)
#define ZBLK 2048  // zeroing blocks fused into the row-FFT launch

// Scratch: FFT intermediate [B, D, WR] complex, interleaved accumulation
// volume [D, D, WR] of float4 (num_re, num_im, wvol, cvol).
__device__ float2 g_f[(size_t)NB * DD * WR];
__device__ float4 g_vol[(size_t)DD * DD * WR];

__device__ __forceinline__ void red_add_v4(float4* addr, float4 v) {
    asm volatile("red.global.add.v4.f32 [%0], {%1, %2, %3, %4};"
                 :: "l"(addr), "f"(v.x), "f"(v.y), "f"(v.z), "f"(v.w) : "memory");
}

__device__ __forceinline__ void flush_corner(int z, int y, int x, float4 v) {
    if ((unsigned)z < DD && (unsigned)y < DD && (unsigned)x < WR && v.z != 0.0f)
        red_add_v4(&g_vol[((size_t)z * DD + y) * WR + x], v);
}

// tw[j] = exp(-2*pi*i*j/256), j < 128.
__device__ __forceinline__ void init_twiddles(float2* tw, int t) {
    float ang = (2.0f * PI_F / 256.0f) * (float)t;
    float s, c;
    sincosf(ang, &s, &c);
    tw[t] = make_float2(c, -s);
}

// In-place 256-point radix-2 DIT FFT (input must be in bit-reversed order).
__device__ __forceinline__ void fft256_dit(float2* sh, const float2* tw, int t) {
#pragma unroll
    for (int len = 2; len <= 256; len <<= 1) {
        int half = len >> 1;
        int j = t & (half - 1);
        int i = ((t - j) << 1) + j;
        float2 w = tw[j * (256 / len)];
        float2 u = sh[i];
        float2 v = sh[i + half];
        float2 vw = make_float2(v.x * w.x - v.y * w.y, v.x * w.y + v.y * w.x);
        sh[i]        = make_float2(u.x + vw.x, u.y + vw.y);
        sh[i + half] = make_float2(u.x - vw.x, u.y - vw.y);
        __syncthreads();
    }
}

// Fused kernel: first ZBLK blocks zero g_vol (pure DRAM stores), remaining
// blocks do the row FFTs (two real rows packed into one complex FFT).
// The two roles are independent and overlap on the chip in one launch.
__global__ void row_fft_zero_kernel(const float* __restrict__ imgs) {
    if (blockIdx.x < ZBLK) {
        const size_t P = (size_t)DD * DD * WR;
        size_t stride = (size_t)ZBLK * blockDim.x;
        const float4 Z4 = make_float4(0.0f, 0.0f, 0.0f, 0.0f);
        for (size_t i = (size_t)blockIdx.x * blockDim.x + threadIdx.x; i < P; i += stride)
            g_vol[i] = Z4;
        return;
    }
    __shared__ float2 sh[256];
    __shared__ float2 tw[128];
    int t = threadIdx.x;                 // 128 threads
    int pair = blockIdx.x - ZBLK;
    int b = pair >> 7;
    int r = pair & 127;
    init_twiddles(tw, t);
    const float* A = imgs + ((size_t)b * DD + 2 * r) * DD;
    const float* Bv = A + DD;
    int i0 = __brev(t) >> 24;
    int i1 = __brev(t + 128) >> 24;
    sh[t]       = make_float2(A[i0], Bv[i0]);
    sh[t + 128] = make_float2(A[i1], Bv[i1]);
    __syncthreads();
    fft256_dit(sh, tw, t);

    float2 Zk = sh[t];
    float2 Zn = sh[(256 - t) & 255];
    float2 Fa = make_float2(0.5f * (Zk.x + Zn.x), 0.5f * (Zk.y - Zn.y));
    float2 Fb = make_float2(0.5f * (Zk.y + Zn.y), -0.5f * (Zk.x - Zn.x));
    float2* dstA = g_f + ((size_t)b * DD + 2 * r) * WR;
    float2* dstB = dstA + WR;
    dstA[t] = Fa;
    dstB[t] = Fb;
    if (t == 0) {
        float2 Z = sh[128];
        dstA[128] = make_float2(Z.x, 0.0f);
        dstB[128] = make_float2(Z.y, 0.0f);
    }
}

// Column FFT along y for 16 columns per block, coalesced loads/stores.
// DIF; write index = brev(i) ^ 128 folds bit-reversal + fftshift.
__global__ void col_fft_kernel() {
    __shared__ float2 sh[256][17];
    __shared__ float2 tw[128];
    int t = threadIdx.x;                 // 256 threads
    if (t < 128) init_twiddles(tw, t);
    int b = blockIdx.x / 9;
    int tile = blockIdx.x - b * 9;
    int x0 = tile * 16;
    int c = t & 15;
    int g = t >> 4;
    int x = x0 + c;
    bool act = x < WR;
    float2* base = g_f + (size_t)b * DD * WR;
#pragma unroll
    for (int i = 0; i < 16; i++) {
        int row = i * 16 + g;
        sh[row][c] = act ? base[(size_t)row * WR + x] : make_float2(0.0f, 0.0f);
    }
    __syncthreads();
#pragma unroll
    for (int s = 0; s < 8; s++) {
        int half = 128 >> s;
#pragma unroll
        for (int jj = 0; jj < 8; jj++) {
            int bj = (g << 3) + jj;
            int j = bj & (half - 1);
            int i = ((bj - j) << 1) + j;
            float2 w = tw[j << s];
            float2 u = sh[i][c];
            float2 v = sh[i + half][c];
            sh[i][c] = make_float2(u.x + v.x, u.y + v.y);
            float2 d = make_float2(u.x - v.x, u.y - v.y);
            sh[i + half][c] = make_float2(d.x * w.x - d.y * w.y,
                                          d.x * w.y + d.y * w.x);
        }
        __syncthreads();
    }
    if (act) {
#pragma unroll
        for (int i = 0; i < 16; i++) {
            int row = i * 16 + g;
            int yd = (__brev(row) >> 24) ^ 128;
            base[(size_t)yd * WR + x] = sh[row][c];
        }
    }
}

// Scatter with run-merging. Loads for the whole run are prefetched up-front
// (batched -> high MLP), then the merge/flush walk is pure register + REDG work.
__global__ void __launch_bounds__(256, 3)
scatter_kernel(const float* __restrict__ ctf,
               const float* __restrict__ rotm,
               const float* __restrict__ hw) {
    int tid = blockIdx.x * blockDim.x + threadIdx.x;
    const int TT = NB * DD * NCH;
    if (tid >= TT) return;
    int ch = tid % NCH;
    int t2 = tid / NCH;
    int y = t2 & 255;
    int b = t2 >> 8;
    int xs = ch * RUN;
    int n = min(RUN, WR - xs);

    size_t rowoff = ((size_t)b * DD + y) * WR + xs;

    // -------- prefetch phase (independent loads, MLP ~ 12) --------
    float2 fv8[RUN];
    float cv8[RUN];
#pragma unroll
    for (int i = 0; i < RUN; i++)
        if (i < n) fv8[i] = __ldg(&g_f[rowoff + i]);
#pragma unroll
    for (int i = 0; i < RUN; i++)
        if (i < n) cv8[i] = __ldg(&ctf[rowoff + i]);

    float ky = (float)(y - 128);
    float sy = hw[2 * b + 0];
    float sx = hw[2 * b + 1];
    const float* M = rotm + b * 9;
    float m2 = M[2], m5 = M[5], m8 = M[8];
    float p0 = M[1] * ky, p1 = M[4] * ky, p2 = M[7] * ky;

    const float C = -2.0f * PI_F / 256.0f;
    float cs, sn, cd, sd;
    sincosf(C * (ky * sy + (float)xs * sx), &sn, &cs);
    sincosf(C * sx, &sd, &cd);

    float4 a0, a1, a2, a3, a4, a5, a6, a7;   // index bits: (z<<2)|(y<<1)|x
    const float4 Z4 = make_float4(0.0f, 0.0f, 0.0f, 0.0f);
    a0 = a1 = a2 = a3 = a4 = a5 = a6 = a7 = Z4;
    int bz = 0, by_ = 0, bx = 0;
    bool have = false;

#pragma unroll
    for (int i = 0; i < RUN; i++) {
        if (i >= n) break;
        int x = xs + i;
        float kx = (float)x;
        float2 f = fv8[i];
        float cv = cv8[i];

        float vr = cv * (f.x * cs - f.y * sn);
        float vi = cv * (f.x * sn + f.y * cs);
        float csq = cv * cv;
        float ncs = cs * cd - sn * sd;
        float nsn = sn * cd + cs * sd;
        cs = ncs; sn = nsn;

        float r0 = p0 + m2 * kx;
        float r1 = p1 + m5 * kx;
        float r2 = p2 + m8 * kx;
        if (r2 < 0.0f) { r0 = -r0; r1 = -r1; r2 = -r2; vi = -vi; }

        float zc = r0 + 128.0f, yc = r1 + 128.0f, xc = r2;
        float z0f = floorf(zc), y0f = floorf(yc), x0f = floorf(xc);
        float fz = zc - z0f, fy = yc - y0f, fx = xc - x0f;
        int z0 = (int)z0f, y0 = (int)y0f, x0 = (int)x0f;
        float gz = 1.0f - fz, gy = 1.0f - fy, gx = 1.0f - fx;
        float w0 = gz * gy * gx, w1 = gz * gy * fx;
        float w2 = gz * fy * gx, w3 = gz * fy * fx;
        float w4 = fz * gy * gx, w5 = fz * gy * fx;
        float w6 = fz * fy * gx, w7 = fz * fy * fx;

        bool reinit = !have;
        if (have) {
            int dz = z0 - bz, dy = y0 - by_, dx = x0 - bx;
            if ((unsigned)(dz + 1) > 2u || (unsigned)(dy + 1) > 2u ||
                (unsigned)(dx + 1) > 2u) {
                flush_corner(bz,     by_,     bx,     a0);
                flush_corner(bz,     by_,     bx + 1, a1);
                flush_corner(bz,     by_ + 1, bx,     a2);
                flush_corner(bz,     by_ + 1, bx + 1, a3);
                flush_corner(bz + 1, by_,     bx,     a4);
                flush_corner(bz + 1, by_,     bx + 1, a5);
                flush_corner(bz + 1, by_ + 1, bx,     a6);
                flush_corner(bz + 1, by_ + 1, bx + 1, a7);
                reinit = true;
            } else {
#define SURV(oz, oy, ox) (((unsigned)((oz) - dz) <= 1u) && \
                          ((unsigned)((oy) - dy) <= 1u) && \
                          ((unsigned)((ox) - dx) <= 1u))
                if (!SURV(0,0,0)) flush_corner(bz,     by_,     bx,     a0);
                if (!SURV(0,0,1)) flush_corner(bz,     by_,     bx + 1, a1);
                if (!SURV(0,1,0)) flush_corner(bz,     by_ + 1, bx,     a2);
                if (!SURV(0,1,1)) flush_corner(bz,     by_ + 1, bx + 1, a3);
                if (!SURV(1,0,0)) flush_corner(bz + 1, by_,     bx,     a4);
                if (!SURV(1,0,1)) flush_corner(bz + 1, by_,     bx + 1, a5);
                if (!SURV(1,1,0)) flush_corner(bz + 1, by_ + 1, bx,     a6);
                if (!SURV(1,1,1)) flush_corner(bz + 1, by_ + 1, bx + 1, a7);
#undef SURV
                if (dz == 1)       { a0=a4; a1=a5; a2=a6; a3=a7; a4=Z4; a5=Z4; a6=Z4; a7=Z4; }
                else if (dz == -1) { a4=a0; a5=a1; a6=a2; a7=a3; a0=Z4; a1=Z4; a2=Z4; a3=Z4; }
                if (dy == 1)       { a0=a2; a1=a3; a4=a6; a5=a7; a2=Z4; a3=Z4; a6=Z4; a7=Z4; }
                else if (dy == -1) { a2=a0; a3=a1; a6=a4; a7=a5; a0=Z4; a1=Z4; a4=Z4; a5=Z4; }
                if (dx == 1)       { a0=a1; a2=a3; a4=a5; a6=a7; a1=Z4; a3=Z4; a5=Z4; a7=Z4; }
                else if (dx == -1) { a1=a0; a3=a2; a5=a4; a7=a6; a0=Z4; a2=Z4; a4=Z4; a6=Z4; }
                bz = z0; by_ = y0; bx = x0;
                a0.x += w0*vr; a0.y += w0*vi; a0.z += w0; a0.w += w0*csq;
                a1.x += w1*vr; a1.y += w1*vi; a1.z += w1; a1.w += w1*csq;
                a2.x += w2*vr; a2.y += w2*vi; a2.z += w2; a2.w += w2*csq;
                a3.x += w3*vr; a3.y += w3*vi; a3.z += w3; a3.w += w3*csq;
                a4.x += w4*vr; a4.y += w4*vi; a4.z += w4; a4.w += w4*csq;
                a5.x += w5*vr; a5.y += w5*vi; a5.z += w5; a5.w += w5*csq;
                a6.x += w6*vr; a6.y += w6*vi; a6.z += w6; a6.w += w6*csq;
                a7.x += w7*vr; a7.y += w7*vi; a7.z += w7; a7.w += w7*csq;
            }
        }
        if (reinit) {
            bz = z0; by_ = y0; bx = x0; have = true;
            a0 = make_float4(w0*vr, w0*vi, w0, w0*csq);
            a1 = make_float4(w1*vr, w1*vi, w1, w1*csq);
            a2 = make_float4(w2*vr, w2*vi, w2, w2*csq);
            a3 = make_float4(w3*vr, w3*vi, w3, w3*csq);
            a4 = make_float4(w4*vr, w4*vi, w4, w4*csq);
            a5 = make_float4(w5*vr, w5*vi, w5, w5*csq);
            a6 = make_float4(w6*vr, w6*vi, w6, w6*csq);
            a7 = make_float4(w7*vr, w7*vi, w7, w7*csq);
        }
    }
    if (have) {
        flush_corner(bz,     by_,     bx,     a0);
        flush_corner(bz,     by_,     bx + 1, a1);
        flush_corner(bz,     by_ + 1, bx,     a2);
        flush_corner(bz,     by_ + 1, bx + 1, a3);
        flush_corner(bz + 1, by_,     bx,     a4);
        flush_corner(bz + 1, by_,     bx + 1, a5);
        flush_corner(bz + 1, by_ + 1, bx,     a6);
        flush_corner(bz + 1, by_ + 1, bx + 1, a7);
    }
}

// De-interleave: each thread transposes 4 consecutive float4s into one
// 16B store per output plane.
__global__ void finalize_kernel(float* __restrict__ out) {
    const size_t P = (size_t)DD * DD * WR;      // divisible by 4
    const size_t Q = P / 4;
    size_t stride = (size_t)gridDim.x * blockDim.x;
    float4* o0 = (float4*)out;
    float4* o1 = (float4*)(out + P);
    float4* o2 = (float4*)(out + 2 * P);
    float4* o3 = (float4*)(out + 3 * P);
    for (size_t q = (size_t)blockIdx.x * blockDim.x + threadIdx.x; q < Q; q += stride) {
        float4 v0 = g_vol[4 * q + 0];
        float4 v1 = g_vol[4 * q + 1];
        float4 v2 = g_vol[4 * q + 2];
        float4 v3 = g_vol[4 * q + 3];
        o0[q] = make_float4(v0.x, v1.x, v2.x, v3.x);
        o1[q] = make_float4(v0.y, v1.y, v2.y, v3.y);
        o2[q] = make_float4(v0.z, v1.z, v2.z, v3.z);
        o3[q] = make_float4(v0.w, v1.w, v2.w, v3.w);
    }
}

extern "C" void kernel_launch(void* const* d_in, const int* in_sizes, int n_in,
                              void* d_out, int out_size) {
    const float* imgs = (const float*)d_in[0];
    const float* ctf  = (const float*)d_in[1];
    const float* rotm = (const float*)d_in[2];
    const float* hw   = (const float*)d_in[3];
    float* out = (float*)d_out;

    row_fft_zero_kernel<<<ZBLK + NB * 128, 128>>>(imgs);
    col_fft_kernel<<<NB * 9, 256>>>();
    const int TT = NB * DD * NCH;
    scatter_kernel<<<(TT + 255) / 256, 256>>>(ctf, rotm, hw);
    finalize_kernel<<<2048, 256>>>(out);
}

// round 5
// speedup vs baseline: 1.1020x; 1.1020x over previous
#include <cuda_runtime.h>
#include <cstdint>

#define DD 256
#define WR 129
#define NB 64
#define PI_F 3.14159265358979323846f
#define RUN 8
#define NCH 17   // ceil(129/8)
#define ZBLK 2048                 // zero-role blocks inside the fused launch
#define FFTBLK (NB * 128)         // 8192 FFT-role blocks
#define TOTBLK (ZBLK + FFTBLK)    // 10240, ZBLK = TOTBLK/5 exactly

// Scratch: FFT intermediate [B, D, WR] complex, interleaved accumulation
// volume [D, D, WR] of float4 (num_re, num_im, wvol, cvol).
__device__ float2 g_f[(size_t)NB * DD * WR];
__device__ float4 g_vol[(size_t)DD * DD * WR];

__device__ __forceinline__ void red_add_v4(float4* addr, float4 v) {
    asm volatile("red.global.add.v4.f32 [%0], {%1, %2, %3, %4};"
                 :: "l"(addr), "f"(v.x), "f"(v.y), "f"(v.z), "f"(v.w) : "memory");
}

__device__ __forceinline__ void flush_corner(int z, int y, int x, float4 v) {
    if ((unsigned)z < DD && (unsigned)y < DD && (unsigned)x < WR && v.z != 0.0f)
        red_add_v4(&g_vol[((size_t)z * DD + y) * WR + x], v);
}

// tw[j] = exp(-2*pi*i*j/256), j < 128.
__device__ __forceinline__ void init_twiddles(float2* tw, int t) {
    float ang = (2.0f * PI_F / 256.0f) * (float)t;
    float s, c;
    sincosf(ang, &s, &c);
    tw[t] = make_float2(c, -s);
}

// In-place 256-point radix-2 DIT FFT (input must be in bit-reversed order).
__device__ __forceinline__ void fft256_dit(float2* sh, const float2* tw, int t) {
#pragma unroll
    for (int len = 2; len <= 256; len <<= 1) {
        int half = len >> 1;
        int j = t & (half - 1);
        int i = ((t - j) << 1) + j;
        float2 w = tw[j * (256 / len)];
        float2 u = sh[i];
        float2 v = sh[i + half];
        float2 vw = make_float2(v.x * w.x - v.y * w.y, v.x * w.y + v.y * w.x);
        sh[i]        = make_float2(u.x + vw.x, u.y + vw.y);
        sh[i + half] = make_float2(u.x - vw.x, u.y - vw.y);
        __syncthreads();
    }
}

// Fused kernel: every 5th block zeroes a stripe of g_vol (DRAM-bound role,
// interleaved so every wave mixes zero + FFT blocks); the rest do row FFTs
// (two real rows packed into one complex FFT, split afterwards).
__global__ void row_fft_zero_kernel(const float* __restrict__ imgs) {
    if ((blockIdx.x % 5) == 4) {
        int zidx = blockIdx.x / 5;               // 0 .. ZBLK-1
        const size_t P = (size_t)DD * DD * WR;
        size_t stride = (size_t)ZBLK * blockDim.x;
        const float4 Z4 = make_float4(0.0f, 0.0f, 0.0f, 0.0f);
        for (size_t i = (size_t)zidx * blockDim.x + threadIdx.x; i < P; i += stride)
            g_vol[i] = Z4;
        return;
    }
    __shared__ float2 sh[256];
    __shared__ float2 tw[128];
    int t = threadIdx.x;                         // 128 threads
    int pair = blockIdx.x - blockIdx.x / 5;      // compute-role index, 0 .. FFTBLK-1
    int b = pair >> 7;
    int r = pair & 127;
    init_twiddles(tw, t);
    const float* A = imgs + ((size_t)b * DD + 2 * r) * DD;
    const float* Bv = A + DD;
    int i0 = __brev(t) >> 24;
    int i1 = __brev(t + 128) >> 24;
    sh[t]       = make_float2(A[i0], Bv[i0]);
    sh[t + 128] = make_float2(A[i1], Bv[i1]);
    __syncthreads();
    fft256_dit(sh, tw, t);

    float2 Zk = sh[t];
    float2 Zn = sh[(256 - t) & 255];
    float2 Fa = make_float2(0.5f * (Zk.x + Zn.x), 0.5f * (Zk.y - Zn.y));
    float2 Fb = make_float2(0.5f * (Zk.y + Zn.y), -0.5f * (Zk.x - Zn.x));
    float2* dstA = g_f + ((size_t)b * DD + 2 * r) * WR;
    float2* dstB = dstA + WR;
    dstA[t] = Fa;
    dstB[t] = Fb;
    if (t == 0) {
        float2 Z = sh[128];
        dstA[128] = make_float2(Z.x, 0.0f);
        dstB[128] = make_float2(Z.y, 0.0f);
    }
}

// Column FFT along y for 16 columns per block, coalesced loads/stores.
// DIF; write index = brev(i) ^ 128 folds bit-reversal + fftshift.
__global__ void col_fft_kernel() {
    __shared__ float2 sh[256][17];
    __shared__ float2 tw[128];
    int t = threadIdx.x;                 // 256 threads
    if (t < 128) init_twiddles(tw, t);
    int b = blockIdx.x / 9;
    int tile = blockIdx.x - b * 9;
    int x0 = tile * 16;
    int c = t & 15;
    int g = t >> 4;
    int x = x0 + c;
    bool act = x < WR;
    float2* base = g_f + (size_t)b * DD * WR;
#pragma unroll
    for (int i = 0; i < 16; i++) {
        int row = i * 16 + g;
        sh[row][c] = act ? base[(size_t)row * WR + x] : make_float2(0.0f, 0.0f);
    }
    __syncthreads();
#pragma unroll
    for (int s = 0; s < 8; s++) {
        int half = 128 >> s;
#pragma unroll
        for (int jj = 0; jj < 8; jj++) {
            int bj = (g << 3) + jj;
            int j = bj & (half - 1);
            int i = ((bj - j) << 1) + j;
            float2 w = tw[j << s];
            float2 u = sh[i][c];
            float2 v = sh[i + half][c];
            sh[i][c] = make_float2(u.x + v.x, u.y + v.y);
            float2 d = make_float2(u.x - v.x, u.y - v.y);
            sh[i + half][c] = make_float2(d.x * w.x - d.y * w.y,
                                          d.x * w.y + d.y * w.x);
        }
        __syncthreads();
    }
    if (act) {
#pragma unroll
        for (int i = 0; i < 16; i++) {
            int row = i * 16 + g;
            int yd = (__brev(row) >> 24) ^ 128;
            base[(size_t)yd * WR + x] = sh[row][c];
        }
    }
}

// Scatter with run-merging. Loads for the whole run are prefetched up-front
// (batched -> high MLP), then the merge/flush walk is pure register + REDG work.
__global__ void scatter_kernel(const float* __restrict__ ctf,
                               const float* __restrict__ rotm,
                               const float* __restrict__ hw) {
    int tid = blockIdx.x * blockDim.x + threadIdx.x;
    const int TT = NB * DD * NCH;
    if (tid >= TT) return;
    int ch = tid % NCH;
    int t2 = tid / NCH;
    int y = t2 & 255;
    int b = t2 >> 8;
    int xs = ch * RUN;
    int n = min(RUN, WR - xs);

    size_t rowoff = ((size_t)b * DD + y) * WR + xs;

    // -------- prefetch phase (independent loads, MLP ~ 12) --------
    float2 fv8[RUN];
    float cv8[RUN];
#pragma unroll
    for (int i = 0; i < RUN; i++)
        if (i < n) fv8[i] = __ldg(&g_f[rowoff + i]);
#pragma unroll
    for (int i = 0; i < RUN; i++)
        if (i < n) cv8[i] = __ldg(&ctf[rowoff + i]);

    float ky = (float)(y - 128);
    float sy = hw[2 * b + 0];
    float sx = hw[2 * b + 1];
    const float* M = rotm + b * 9;
    float m2 = M[2], m5 = M[5], m8 = M[8];
    float p0 = M[1] * ky, p1 = M[4] * ky, p2 = M[7] * ky;

    const float C = -2.0f * PI_F / 256.0f;
    float cs, sn, cd, sd;
    sincosf(C * (ky * sy + (float)xs * sx), &sn, &cs);
    sincosf(C * sx, &sd, &cd);

    float4 a0, a1, a2, a3, a4, a5, a6, a7;   // index bits: (z<<2)|(y<<1)|x
    const float4 Z4 = make_float4(0.0f, 0.0f, 0.0f, 0.0f);
    a0 = a1 = a2 = a3 = a4 = a5 = a6 = a7 = Z4;
    int bz = 0, by_ = 0, bx = 0;
    bool have = false;

#pragma unroll
    for (int i = 0; i < RUN; i++) {
        if (i >= n) break;
        int x = xs + i;
        float kx = (float)x;
        float2 f = fv8[i];
        float cv = cv8[i];

        float vr = cv * (f.x * cs - f.y * sn);
        float vi = cv * (f.x * sn + f.y * cs);
        float csq = cv * cv;
        float ncs = cs * cd - sn * sd;
        float nsn = sn * cd + cs * sd;
        cs = ncs; sn = nsn;

        float r0 = p0 + m2 * kx;
        float r1 = p1 + m5 * kx;
        float r2 = p2 + m8 * kx;
        if (r2 < 0.0f) { r0 = -r0; r1 = -r1; r2 = -r2; vi = -vi; }

        float zc = r0 + 128.0f, yc = r1 + 128.0f, xc = r2;
        float z0f = floorf(zc), y0f = floorf(yc), x0f = floorf(xc);
        float fz = zc - z0f, fy = yc - y0f, fx = xc - x0f;
        int z0 = (int)z0f, y0 = (int)y0f, x0 = (int)x0f;
        float gz = 1.0f - fz, gy = 1.0f - fy, gx = 1.0f - fx;
        float w0 = gz * gy * gx, w1 = gz * gy * fx;
        float w2 = gz * fy * gx, w3 = gz * fy * fx;
        float w4 = fz * gy * gx, w5 = fz * gy * fx;
        float w6 = fz * fy * gx, w7 = fz * fy * fx;

        bool reinit = !have;
        if (have) {
            int dz = z0 - bz, dy = y0 - by_, dx = x0 - bx;
            if ((unsigned)(dz + 1) > 2u || (unsigned)(dy + 1) > 2u ||
                (unsigned)(dx + 1) > 2u) {
                flush_corner(bz,     by_,     bx,     a0);
                flush_corner(bz,     by_,     bx + 1, a1);
                flush_corner(bz,     by_ + 1, bx,     a2);
                flush_corner(bz,     by_ + 1, bx + 1, a3);
                flush_corner(bz + 1, by_,     bx,     a4);
                flush_corner(bz + 1, by_,     bx + 1, a5);
                flush_corner(bz + 1, by_ + 1, bx,     a6);
                flush_corner(bz + 1, by_ + 1, bx + 1, a7);
                reinit = true;
            } else {
#define SURV(oz, oy, ox) (((unsigned)((oz) - dz) <= 1u) && \
                          ((unsigned)((oy) - dy) <= 1u) && \
                          ((unsigned)((ox) - dx) <= 1u))
                if (!SURV(0,0,0)) flush_corner(bz,     by_,     bx,     a0);
                if (!SURV(0,0,1)) flush_corner(bz,     by_,     bx + 1, a1);
                if (!SURV(0,1,0)) flush_corner(bz,     by_ + 1, bx,     a2);
                if (!SURV(0,1,1)) flush_corner(bz,     by_ + 1, bx + 1, a3);
                if (!SURV(1,0,0)) flush_corner(bz + 1, by_,     bx,     a4);
                if (!SURV(1,0,1)) flush_corner(bz + 1, by_,     bx + 1, a5);
                if (!SURV(1,1,0)) flush_corner(bz + 1, by_ + 1, bx,     a6);
                if (!SURV(1,1,1)) flush_corner(bz + 1, by_ + 1, bx + 1, a7);
#undef SURV
                if (dz == 1)       { a0=a4; a1=a5; a2=a6; a3=a7; a4=Z4; a5=Z4; a6=Z4; a7=Z4; }
                else if (dz == -1) { a4=a0; a5=a1; a6=a2; a7=a3; a0=Z4; a1=Z4; a2=Z4; a3=Z4; }
                if (dy == 1)       { a0=a2; a1=a3; a4=a6; a5=a7; a2=Z4; a3=Z4; a6=Z4; a7=Z4; }
                else if (dy == -1) { a2=a0; a3=a1; a6=a4; a7=a5; a0=Z4; a1=Z4; a4=Z4; a5=Z4; }
                if (dx == 1)       { a0=a1; a2=a3; a4=a5; a6=a7; a1=Z4; a3=Z4; a5=Z4; a7=Z4; }
                else if (dx == -1) { a1=a0; a3=a2; a5=a4; a7=a6; a0=Z4; a2=Z4; a4=Z4; a6=Z4; }
                bz = z0; by_ = y0; bx = x0;
                a0.x += w0*vr; a0.y += w0*vi; a0.z += w0; a0.w += w0*csq;
                a1.x += w1*vr; a1.y += w1*vi; a1.z += w1; a1.w += w1*csq;
                a2.x += w2*vr; a2.y += w2*vi; a2.z += w2; a2.w += w2*csq;
                a3.x += w3*vr; a3.y += w3*vi; a3.z += w3; a3.w += w3*csq;
                a4.x += w4*vr; a4.y += w4*vi; a4.z += w4; a4.w += w4*csq;
                a5.x += w5*vr; a5.y += w5*vi; a5.z += w5; a5.w += w5*csq;
                a6.x += w6*vr; a6.y += w6*vi; a6.z += w6; a6.w += w6*csq;
                a7.x += w7*vr; a7.y += w7*vi; a7.z += w7; a7.w += w7*csq;
            }
        }
        if (reinit) {
            bz = z0; by_ = y0; bx = x0; have = true;
            a0 = make_float4(w0*vr, w0*vi, w0, w0*csq);
            a1 = make_float4(w1*vr, w1*vi, w1, w1*csq);
            a2 = make_float4(w2*vr, w2*vi, w2, w2*csq);
            a3 = make_float4(w3*vr, w3*vi, w3, w3*csq);
            a4 = make_float4(w4*vr, w4*vi, w4, w4*csq);
            a5 = make_float4(w5*vr, w5*vi, w5, w5*csq);
            a6 = make_float4(w6*vr, w6*vi, w6, w6*csq);
            a7 = make_float4(w7*vr, w7*vi, w7, w7*csq);
        }
    }
    if (have) {
        flush_corner(bz,     by_,     bx,     a0);
        flush_corner(bz,     by_,     bx + 1, a1);
        flush_corner(bz,     by_ + 1, bx,     a2);
        flush_corner(bz,     by_ + 1, bx + 1, a3);
        flush_corner(bz + 1, by_,     bx,     a4);
        flush_corner(bz + 1, by_,     bx + 1, a5);
        flush_corner(bz + 1, by_ + 1, bx,     a6);
        flush_corner(bz + 1, by_ + 1, bx + 1, a7);
    }
}

// De-interleave: each thread transposes 4 consecutive float4s into one
// 16B store per output plane. Streaming loads (no reuse of g_vol).
__global__ void finalize_kernel(float* __restrict__ out) {
    const size_t P = (size_t)DD * DD * WR;      // divisible by 4
    const size_t Q = P / 4;
    size_t stride = (size_t)gridDim.x * blockDim.x;
    float4* o0 = (float4*)out;
    float4* o1 = (float4*)(out + P);
    float4* o2 = (float4*)(out + 2 * P);
    float4* o3 = (float4*)(out + 3 * P);
    for (size_t q = (size_t)blockIdx.x * blockDim.x + threadIdx.x; q < Q; q += stride) {
        float4 v0 = __ldcs(&g_vol[4 * q + 0]);
        float4 v1 = __ldcs(&g_vol[4 * q + 1]);
        float4 v2 = __ldcs(&g_vol[4 * q + 2]);
        float4 v3 = __ldcs(&g_vol[4 * q + 3]);
        o0[q] = make_float4(v0.x, v1.x, v2.x, v3.x);
        o1[q] = make_float4(v0.y, v1.y, v2.y, v3.y);
        o2[q] = make_float4(v0.z, v1.z, v2.z, v3.z);
        o3[q] = make_float4(v0.w, v1.w, v2.w, v3.w);
    }
}

extern "C" void kernel_launch(void* const* d_in, const int* in_sizes, int n_in,
                              void* d_out, int out_size) {
    const float* imgs = (const float*)d_in[0];
    const float* ctf  = (const float*)d_in[1];
    const float* rotm = (const float*)d_in[2];
    const float* hw   = (const float*)d_in[3];
    float* out = (float*)d_out;

    row_fft_zero_kernel<<<TOTBLK, 128>>>(imgs);
    col_fft_kernel<<<NB * 9, 256>>>();
    const int TT = NB * DD * NCH;
    scatter_kernel<<<(TT + 255) / 256, 256>>>(ctf, rotm, hw);
    finalize_kernel<<<4096, 256>>>(out);
}